// round 10
// baseline (speedup 1.0000x reference)
#include <cuda_runtime.h>
#include <cuda_bf16.h>
#include <cstdint>

#define SHIFT 4
#define NR 225
#define AS 132
#define ES 36
#define TS 40
#define SCALE 0.17677669529663687f

#define SA_B   0
#define QEB_B  67584
#define KEB_B  86016
#define VEB_B  104448
#define QH_B   122880
#define QL_B   133120
#define KH_B   143360
#define KL_B   153600
#define VTH_B  163840
#define VTL_B  172544
#define OE_B   181248
#define SMEM_BYTES 199680
#define AH_B   67584
#define AL_B   122880

__device__ __forceinline__ void mma_bf16(float* d, uint32_t a0, uint32_t a1, uint32_t a2, uint32_t a3,
                                         uint32_t b0, uint32_t b1) {
    asm volatile(
        "mma.sync.aligned.m16n8k16.row.col.f32.bf16.bf16.f32 "
        "{%0,%1,%2,%3},{%4,%5,%6,%7},{%8,%9},{%0,%1,%2,%3};"
        : "+f"(d[0]), "+f"(d[1]), "+f"(d[2]), "+f"(d[3])
        : "r"(a0), "r"(a1), "r"(a2), "r"(a3), "r"(b0), "r"(b1));
}
__device__ __forceinline__ uint32_t pkhi(float a, float b) {
    __nv_bfloat162 t = __floats2bfloat162_rn(a, b);
    return *reinterpret_cast<uint32_t*>(&t);
}
__device__ __forceinline__ uint32_t pklo(float a, float b) {
    float ha = __bfloat162float(__float2bfloat16(a));
    float hb = __bfloat162float(__float2bfloat16(b));
    __nv_bfloat162 t = __floats2bfloat162_rn(a - ha, b - hb);
    return *reinterpret_cast<uint32_t*>(&t);
}
__device__ __forceinline__ float2 rec2(uint32_t h, uint32_t l) {
    float2 a = __bfloat1622float2(*reinterpret_cast<__nv_bfloat162*>(&h));
    float2 b = __bfloat1622float2(*reinterpret_cast<__nv_bfloat162*>(&l));
    return make_float2(a.x + b.x, a.y + b.y);
}
__device__ __forceinline__ float2 upk(uint32_t h) {
    return __bfloat1622float2(*reinterpret_cast<__nv_bfloat162*>(&h));
}

__global__ __launch_bounds__(256, 1)
void swin_attn_kernel(const float* __restrict__ qkv,
                      const float* __restrict__ mask,
                      const float* __restrict__ rpe,
                      float* __restrict__ out)
{
    extern __shared__ char smc[];
    float* sA  = (float*)(smc + SA_B);
    __nv_bfloat16* QEb = (__nv_bfloat16*)(smc + QEB_B);
    __nv_bfloat16* KEb = (__nv_bfloat16*)(smc + KEB_B);
    __nv_bfloat16* VEb = (__nv_bfloat16*)(smc + VEB_B);
    float* sOE = (float*)(smc + OE_B);
    uint32_t* QHu = (uint32_t*)(smc + QH_B);
    uint32_t* QLu = (uint32_t*)(smc + QL_B);
    uint32_t* KHu = (uint32_t*)(smc + KH_B);
    uint32_t* KLu = (uint32_t*)(smc + KL_B);
    uint32_t* AHu = (uint32_t*)(smc + AH_B);
    uint32_t* ALu = (uint32_t*)(smc + AL_B);
    uint32_t* VTHu = (uint32_t*)(smc + VTH_B);
    uint32_t* VTLu = (uint32_t*)(smc + VTL_B);

    const int tid = threadIdx.x, wid = tid >> 5, lane = tid & 31;
    const int h   = blockIdx.y;
    const int b   = blockIdx.x >> 8;
    const int win = blockIdx.x & 255;
    const int wi  = win >> 4, wj = win & 15;

    // ---- load q,k,v; emit q/k hi-lo bf16 (token-major) + V^T hi-lo ----
    {
        const int t = tid >> 1, half = tid & 1;
        const int wh = t >> 4, ww = (t >> 1) & 7, n = t & 1;
        const int gy = (wi*8 + wh + SHIFT) & 127;
        const int gx = (wj*8 + ww + SHIFT) & 127;
        const float* base = qkv + (size_t)((((b*128 + gy)*128 + gx)*2 + n)*384) + h*32 + half*16;
        #pragma unroll
        for (int c4 = 0; c4 < 4; c4++) {
            float4 q = ((const float4*)base)[c4];
            float4 k = ((const float4*)(base + 128))[c4];
            float4 v = ((const float4*)(base + 256))[c4];
            q.x *= SCALE; q.y *= SCALE; q.z *= SCALE; q.w *= SCALE;
            const int u = t*20 + half*8 + c4*2;
            QHu[u]   = pkhi(q.x, q.y); QHu[u+1] = pkhi(q.z, q.w);
            QLu[u]   = pklo(q.x, q.y); QLu[u+1] = pklo(q.z, q.w);
            KHu[u]   = pkhi(k.x, k.y); KHu[u+1] = pkhi(k.z, k.w);
            KLu[u]   = pklo(k.x, k.y); KLu[u+1] = pklo(k.z, k.w);
            float vv[4] = {v.x, v.y, v.z, v.w};
            #pragma unroll
            for (int e = 0; e < 4; e++) {
                const int c = half*16 + c4*4 + e;
                __nv_bfloat16 hi = __float2bfloat16(vv[e]);
                __nv_bfloat16 lo = __float2bfloat16(vv[e] - __bfloat162float(hi));
                ((__nv_bfloat16*)VTHu)[c*136 + t] = hi;
                ((__nv_bfloat16*)VTLu)[c*136 + t] = lo;
            }
        }
    }
    // ---- rel-pos tables -> bf16 ----
    for (int idx = tid; idx < NR*24; idx += 256) {
        const int r = idx / 24, s = idx % 24;
        const int sl = s >> 3, c4 = s & 7;
        float4 v = *(const float4*)(rpe + (size_t)r*384 + h*96 + sl*32 + c4*4);
        __nv_bfloat16* dst = (sl == 0) ? QEb : (sl == 1) ? KEb : VEb;
        if (sl == 0) { v.x *= SCALE; v.y *= SCALE; v.z *= SCALE; v.w *= SCALE; }
        uint2 pk;
        pk.x = pkhi(v.x, v.y); pk.y = pkhi(v.z, v.w);
        *(uint2*)(dst + r*TS + c4*4) = pk;
    }
    __syncthreads();

    // ---- pass 1: qk via mma.sync, 64x32 warp tiles ----
    {
        const int rblk = (wid & 1)*64, cblk = (wid >> 1)*32;
        const int r = lane >> 2, cq = lane & 3;
        float acc[4][4][4];
        #pragma unroll
        for (int m = 0; m < 4; m++)
            #pragma unroll
            for (int n = 0; n < 4; n++)
                #pragma unroll
                for (int e = 0; e < 4; e++) acc[m][n][e] = 0.f;
        #pragma unroll
        for (int kt = 0; kt < 2; kt++) {
            uint32_t ah[4][4], al[4][4];
            #pragma unroll
            for (int m = 0; m < 4; m++) {
                const int b0 = (rblk + m*16 + r)*20 + kt*8 + cq;
                const int b1 = b0 + 160;
                ah[m][0] = QHu[b0]; ah[m][1] = QHu[b1]; ah[m][2] = QHu[b0+4]; ah[m][3] = QHu[b1+4];
                al[m][0] = QLu[b0]; al[m][1] = QLu[b1]; al[m][2] = QLu[b0+4]; al[m][3] = QLu[b1+4];
            }
            #pragma unroll
            for (int n = 0; n < 4; n++) {
                const int bi = (cblk + n*8 + r)*20 + kt*8 + cq;
                uint32_t bh0 = KHu[bi], bh1 = KHu[bi+4];
                uint32_t bl0 = KLu[bi], bl1 = KLu[bi+4];
                #pragma unroll
                for (int m = 0; m < 4; m++) {
                    mma_bf16(acc[m][n], ah[m][0], ah[m][1], ah[m][2], ah[m][3], bh0, bh1);
                    mma_bf16(acc[m][n], al[m][0], al[m][1], al[m][2], al[m][3], bh0, bh1);
                    mma_bf16(acc[m][n], ah[m][0], ah[m][1], ah[m][2], ah[m][3], bl0, bl1);
                }
            }
        }
        const float* mrow = mask + (size_t)win*16384;
        #pragma unroll
        for (int m = 0; m < 4; m++) {
            const int i0 = rblk + m*16 + r, i1 = i0 + 8;
            #pragma unroll
            for (int n = 0; n < 4; n++) {
                const int j0 = cblk + n*8 + cq*2;
                float2 m0 = *(const float2*)(mrow + i0*128 + j0);
                float2 m1 = *(const float2*)(mrow + i1*128 + j0);
                *(float2*)(sA + i0*AS + j0) = make_float2(acc[m][n][0] + m0.x, acc[m][n][1] + m0.y);
                *(float2*)(sA + i1*AS + j0) = make_float2(acc[m][n][2] + m1.x, acc[m][n][3] + m1.y);
            }
        }
    }
    __syncthreads();

    // ---- pass 2: qr term ----
    {
        const int p = tid >> 2, pj0 = (tid & 3) << 4;
        const int phi = p >> 3, pwi = p & 7, i0 = 2*p;
        float4 q0[8], q1[8];
        #pragma unroll
        for (int c4 = 0; c4 < 8; c4++) {
            float2 xy = rec2(QHu[i0*20 + c4*2],     QLu[i0*20 + c4*2]);
            float2 zw = rec2(QHu[i0*20 + c4*2 + 1], QLu[i0*20 + c4*2 + 1]);
            q0[c4] = make_float4(xy.x, xy.y, zw.x, zw.y);
            xy = rec2(QHu[(i0+1)*20 + c4*2],     QLu[(i0+1)*20 + c4*2]);
            zw = rec2(QHu[(i0+1)*20 + c4*2 + 1], QLu[(i0+1)*20 + c4*2 + 1]);
            q1[c4] = make_float4(xy.x, xy.y, zw.x, zw.y);
        }
        #pragma unroll 4
        for (int pj = pj0; pj < pj0 + 16; pj++) {
            const int r = (phi - (pj >> 3) + 7)*15 + (pwi - (pj & 7) + 7);
            float s0 = 0.f, s1 = 0.f;
            #pragma unroll
            for (int c4 = 0; c4 < 8; c4++) {
                uint2 e = *(const uint2*)(KEb + r*TS + c4*4);
                float2 e01 = upk(e.x), e23 = upk(e.y);
                s0 += q0[c4].x*e01.x + q0[c4].y*e01.y + q0[c4].z*e23.x + q0[c4].w*e23.y;
                s1 += q1[c4].x*e01.x + q1[c4].y*e01.y + q1[c4].z*e23.x + q1[c4].w*e23.y;
            }
            float2* d0 = (float2*)(sA + i0*AS + 2*pj);
            float2* d1 = (float2*)(sA + (i0+1)*AS + 2*pj);
            float2 t0 = *d0, t1 = *d1;
            t0.x += s0; t0.y += s0; *d0 = t0;
            t1.x += s1; t1.y += s1; *d1 = t1;
        }
    }
    __syncthreads();

    // ---- pass 3: kr term ----
    {
        const int p = tid >> 2, pi0 = (tid & 3) << 4;
        const int phj = p >> 3, pwj = p & 7, j0 = 2*p;
        float4 k0[8], k1[8];
        #pragma unroll
        for (int c4 = 0; c4 < 8; c4++) {
            float2 xy = rec2(KHu[j0*20 + c4*2],     KLu[j0*20 + c4*2]);
            float2 zw = rec2(KHu[j0*20 + c4*2 + 1], KLu[j0*20 + c4*2 + 1]);
            k0[c4] = make_float4(xy.x, xy.y, zw.x, zw.y);
            xy = rec2(KHu[(j0+1)*20 + c4*2],     KLu[(j0+1)*20 + c4*2]);
            zw = rec2(KHu[(j0+1)*20 + c4*2 + 1], KLu[(j0+1)*20 + c4*2 + 1]);
            k1[c4] = make_float4(xy.x, xy.y, zw.x, zw.y);
        }
        #pragma unroll 4
        for (int pi = pi0; pi < pi0 + 16; pi++) {
            const int r = ((pi >> 3) - phj + 7)*15 + ((pi & 7) - pwj + 7);
            float s0 = 0.f, s1 = 0.f;
            #pragma unroll
            for (int c4 = 0; c4 < 8; c4++) {
                uint2 e = *(const uint2*)(QEb + r*TS + c4*4);
                float2 e01 = upk(e.x), e23 = upk(e.y);
                s0 += k0[c4].x*e01.x + k0[c4].y*e01.y + k0[c4].z*e23.x + k0[c4].w*e23.y;
                s1 += k1[c4].x*e01.x + k1[c4].y*e01.y + k1[c4].z*e23.x + k1[c4].w*e23.y;
            }
            float2* d0 = (float2*)(sA + (2*pi)*AS + j0);
            float2* d1 = (float2*)(sA + (2*pi+1)*AS + j0);
            float2 t0 = *d0, t1 = *d1;
            t0.x += s0; t0.y += s1; *d0 = t0;
            t1.x += s0; t1.y += s1; *d1 = t1;
        }
    }
    __syncthreads();

    // ---- softmax ----
    {
        const int w = tid >> 5, l = tid & 31;
        for (int ii = 0; ii < 16; ii++) {
            const int i = w*16 + ii;
            float v[4];
            #pragma unroll
            for (int k = 0; k < 4; k++) v[k] = sA[i*AS + l + 32*k];
            float m = fmaxf(fmaxf(v[0], v[1]), fmaxf(v[2], v[3]));
            #pragma unroll
            for (int off = 16; off; off >>= 1) m = fmaxf(m, __shfl_xor_sync(~0u, m, off));
            float s = 0.f;
            #pragma unroll
            for (int k = 0; k < 4; k++) { v[k] = __expf(v[k] - m); s += v[k]; }
            #pragma unroll
            for (int off = 16; off; off >>= 1) s += __shfl_xor_sync(~0u, s, off);
            const float inv = 1.f / s;
            #pragma unroll
            for (int k = 0; k < 4; k++) sA[i*AS + l + 32*k] = v[k]*inv;
        }
    }
    __syncthreads();

    // ---- emit attn hi/lo bf16 ----
    {
        const int i = tid >> 1, j0 = (tid & 1)*64;
        #pragma unroll 4
        for (int j = j0; j < j0 + 64; j += 4) {
            float4 a = *(const float4*)(sA + i*AS + j);
            uint2 hv, lv;
            hv.x = pkhi(a.x, a.y); hv.y = pkhi(a.z, a.w);
            lv.x = pklo(a.x, a.y); lv.y = pklo(a.z, a.w);
            *(uint2*)(AHu + i*68 + (j >> 1)) = hv;
            *(uint2*)(ALu + i*68 + (j >> 1)) = lv;
        }
    }
    __syncthreads();

    if (wid < 4) {
        // ---- AV via mma.sync, 32-row tiles, warps 0-3 ----
        const int rblk = wid*32;
        const int r = lane >> 2, cq = lane & 3;
        float acc[2][4][4];
        #pragma unroll
        for (int m = 0; m < 2; m++)
            #pragma unroll
            for (int nt = 0; nt < 4; nt++)
                #pragma unroll
                for (int e = 0; e < 4; e++) acc[m][nt][e] = 0.f;
        #pragma unroll
        for (int kt = 0; kt < 8; kt++) {
            uint32_t ah[2][4], al[2][4];
            #pragma unroll
            for (int m = 0; m < 2; m++) {
                const int b0 = (rblk + m*16 + r)*68 + kt*8 + cq;
                const int b1 = b0 + 544;
                ah[m][0] = AHu[b0]; ah[m][1] = AHu[b1]; ah[m][2] = AHu[b0+4]; ah[m][3] = AHu[b1+4];
                al[m][0] = ALu[b0]; al[m][1] = ALu[b1]; al[m][2] = ALu[b0+4]; al[m][3] = ALu[b1+4];
            }
            #pragma unroll
            for (int nt = 0; nt < 4; nt++) {
                const int bi = (nt*8 + r)*68 + kt*8 + cq;
                uint32_t bh0 = VTHu[bi], bh1 = VTHu[bi+4];
                uint32_t bl0 = VTLu[bi], bl1 = VTLu[bi+4];
                #pragma unroll
                for (int m = 0; m < 2; m++) {
                    mma_bf16(acc[m][nt], ah[m][0], ah[m][1], ah[m][2], ah[m][3], bh0, bh1);
                    mma_bf16(acc[m][nt], al[m][0], al[m][1], al[m][2], al[m][3], bh0, bh1);
                    mma_bf16(acc[m][nt], ah[m][0], ah[m][1], ah[m][2], ah[m][3], bl0, bl1);
                }
            }
        }
        __syncthreads();
        // add embed partial + store
        #pragma unroll
        for (int m = 0; m < 2; m++) {
            #pragma unroll
            for (int half = 0; half < 2; half++) {
                const int i = rblk + m*16 + r + half*8;
                const int p = i >> 1, n = i & 1;
                const int gy = (wi*8 + (p >> 3) + SHIFT) & 127;
                const int gx = (wj*8 + (p & 7) + SHIFT) & 127;
                float* o = out + (size_t)((((b*128 + gy)*128 + gx)*2 + n)*128) + h*32;
                #pragma unroll
                for (int nt = 0; nt < 4; nt++) {
                    const int j = nt*8 + cq*2;
                    float2 e = *(const float2*)(sOE + i*ES + j);
                    float2 rv;
                    rv.x = acc[m][nt][half*2 + 0] + e.x;
                    rv.y = acc[m][nt][half*2 + 1] + e.y;
                    *(float2*)(o + j) = rv;
                }
            }
        }
    } else {
        // ---- scalar v_embed term, warps 4-7 (1 row per thread) -> sOE ----
        const int i = tid - 128;
        const int p = i >> 1;
        const int phi = p >> 3, pwi = p & 7;
        float acc[32];
        #pragma unroll
        for (int c = 0; c < 32; c++) acc[c] = 0.f;
        #pragma unroll 4
        for (int pj = 0; pj < 64; pj++) {
            const float2 A = *(const float2*)(sA + i*AS + 2*pj);
            const float s = A.x + A.y;
            const int r = (phi - (pj >> 3) + 7)*15 + (pwi - (pj & 7) + 7);
            #pragma unroll
            for (int c4 = 0; c4 < 4; c4++) {
                uint2 e = *(const uint2*)(VEb + r*TS + c4*8);
                uint2 e2 = *(const uint2*)(VEb + r*TS + c4*8 + 4);
                float2 f0 = upk(e.x), f1 = upk(e.y), f2 = upk(e2.x), f3 = upk(e2.y);
                acc[c4*8+0] += s*f0.x; acc[c4*8+1] += s*f0.y;
                acc[c4*8+2] += s*f1.x; acc[c4*8+3] += s*f1.y;
                acc[c4*8+4] += s*f2.x; acc[c4*8+5] += s*f2.y;
                acc[c4*8+6] += s*f3.x; acc[c4*8+7] += s*f3.y;
            }
        }
        #pragma unroll
        for (int c4 = 0; c4 < 8; c4++)
            *(float4*)(sOE + i*ES + c4*4) = make_float4(acc[c4*4], acc[c4*4+1], acc[c4*4+2], acc[c4*4+3]);
        __syncthreads();
    }
}

extern "C" void kernel_launch(void* const* d_in, const int* in_sizes, int n_in,
                              void* d_out, int out_size)
{
    const float* qkv  = (const float*)d_in[0];
    const float* mask = (const float*)d_in[1];
    const float* rpe  = (const float*)d_in[2];
    cudaFuncSetAttribute(swin_attn_kernel,
                         cudaFuncAttributeMaxDynamicSharedMemorySize, SMEM_BYTES);
    dim3 grid(1024, 4);
    swin_attn_kernel<<<grid, 256, SMEM_BYTES>>>(qkv, mask, rpe, (float*)d_out);
}